// round 5
// baseline (speedup 1.0000x reference)
#include <cuda_runtime.h>
#include <cuda_bf16.h>
#include <math.h>
#include <stdint.h>

// Problem dims (fixed)
#define B_   16384
#define IN_  512
#define HID_ 1024
#define OUT_ 512
#define KC_  1536
#define N4H  4096

// GEMM tiling
#define BM 128
#define BN 256
#define BK 32
#define NTH 256
#define ASTR 40      // A smem row stride (halves): 32 + 8 pad
#define BSTR 264     // B smem row stride (halves): 256 + 8 pad

// smem layout in halves
#define H_AH  0
#define H_AL  (2 * BM * ASTR)                 // 10240
#define H_BH  (2 * H_AL)                      // 20480
#define H_BL  (H_BH + 2 * BK * BSTR)          // 37376
#define SMEM_HALVES (H_BL + 2 * BK * BSTR)    // 54272
#define SMEM_BYTES  (SMEM_HALVES * 2)         // 108544

// Epilogue staging: 32 rows x 264 f32 (aliases stage smem after sync)
#define ESTR 264

// ---------------------------------------------------------------------------
// Static device scratch
// ---------------------------------------------------------------------------
__device__ __nv_bfloat16 g_Xhi[(size_t)B_ * KC_];
__device__ __nv_bfloat16 g_Xlo[(size_t)B_ * KC_];
__device__ __nv_bfloat16 g_Whi[(size_t)KC_ * N4H];   // [K][4H] concat [i|f|o|c]
__device__ __nv_bfloat16 g_Wlo[(size_t)KC_ * N4H];
__device__ __nv_bfloat16 g_FThi[(size_t)HID_ * OUT_]; // fc_w^T [HID][OUT]
__device__ __nv_bfloat16 g_FTlo[(size_t)HID_ * OUT_];
__device__ __nv_bfloat16 g_Hhi[(size_t)B_ * HID_];
__device__ __nv_bfloat16 g_Hlo[(size_t)B_ * HID_];
__device__ float g_bias[N4H];                         // concat [bi|bf|bo|bc]

// ---------------------------------------------------------------------------
// Helpers
// ---------------------------------------------------------------------------
__device__ __forceinline__ void split_store4(__nv_bfloat16* hi, __nv_bfloat16* lo, float4 v)
{
    float f[4] = {v.x, v.y, v.z, v.w};
    union { __nv_bfloat16 b[4]; uint2 u; } H, L;
    #pragma unroll
    for (int i = 0; i < 4; i++) {
        H.b[i] = __float2bfloat16(f[i]);
        L.b[i] = __float2bfloat16(f[i] - __bfloat162float(H.b[i]));
    }
    *(uint2*)hi = H.u;
    *(uint2*)lo = L.u;
}

__device__ __forceinline__ void cp16(void* sdst, const void* gsrc)
{
    uint32_t s = (uint32_t)__cvta_generic_to_shared(sdst);
    asm volatile("cp.async.cg.shared.global [%0], [%1], 16;" :: "r"(s), "l"(gsrc));
}
__device__ __forceinline__ void cp_commit() { asm volatile("cp.async.commit_group;"); }
__device__ __forceinline__ void cp_wait0()  { asm volatile("cp.async.wait_group 0;"); }

__device__ __forceinline__ void ldm_x4(uint32_t* r, const __nv_bfloat16* p)
{
    uint32_t a = (uint32_t)__cvta_generic_to_shared(p);
    asm volatile("ldmatrix.sync.aligned.m8n8.x4.shared.b16 {%0,%1,%2,%3}, [%4];"
                 : "=r"(r[0]), "=r"(r[1]), "=r"(r[2]), "=r"(r[3]) : "r"(a));
}
__device__ __forceinline__ void ldm_x4t(uint32_t* r, const __nv_bfloat16* p)
{
    uint32_t a = (uint32_t)__cvta_generic_to_shared(p);
    asm volatile("ldmatrix.sync.aligned.m8n8.x4.trans.shared.b16 {%0,%1,%2,%3}, [%4];"
                 : "=r"(r[0]), "=r"(r[1]), "=r"(r[2]), "=r"(r[3]) : "r"(a));
}
__device__ __forceinline__ void mma_bf16(float* c, const uint32_t* a, const uint32_t* b)
{
    asm volatile(
        "mma.sync.aligned.m16n8k16.row.col.f32.bf16.bf16.f32 "
        "{%0,%1,%2,%3}, {%4,%5,%6,%7}, {%8,%9}, {%0,%1,%2,%3};"
        : "+f"(c[0]), "+f"(c[1]), "+f"(c[2]), "+f"(c[3])
        : "r"(a[0]), "r"(a[1]), "r"(a[2]), "r"(a[3]), "r"(b[0]), "r"(b[1]));
}

__device__ __forceinline__ float sigf(float v) { return 1.0f / (1.0f + __expf(-v)); }

// ---------------------------------------------------------------------------
// Conversion kernels (R2-proven)
// ---------------------------------------------------------------------------
__global__ __launch_bounds__(256)
void conv_x_kernel(const float* __restrict__ x, const float* __restrict__ h)
{
    size_t t = (size_t)blockIdx.x * 256 + threadIdx.x;
    size_t m = t / (KC_ / 4);
    int c4 = (int)(t % (KC_ / 4)) * 4;
    float4 v = (c4 < IN_) ? *(const float4*)&x[m * IN_ + c4]
                          : *(const float4*)&h[m * HID_ + (c4 - IN_)];
    split_store4(g_Xhi + m * KC_ + c4, g_Xlo + m * KC_ + c4, v);
}

__global__ __launch_bounds__(256)
void conv_w_kernel(const float* __restrict__ Wi, const float* __restrict__ Wf,
                   const float* __restrict__ Wo, const float* __restrict__ Wc,
                   const float* __restrict__ Ui, const float* __restrict__ Uf,
                   const float* __restrict__ Uo, const float* __restrict__ Uc)
{
    size_t t = (size_t)blockIdx.x * 256 + threadIdx.x;
    int k  = (int)(t / (N4H / 4));
    int c4 = (int)(t % (N4H / 4)) * 4;
    int g  = c4 >> 10;
    int j  = c4 & 1023;
    const float* W = (g == 0) ? Wi : (g == 1) ? Wf : (g == 2) ? Wo : Wc;
    const float* U = (g == 0) ? Ui : (g == 1) ? Uf : (g == 2) ? Uo : Uc;
    float4 v = (k < IN_) ? *(const float4*)&W[(size_t)k * HID_ + j]
                         : *(const float4*)&U[(size_t)(k - IN_) * HID_ + j];
    split_store4(g_Whi + (size_t)k * N4H + c4, g_Wlo + (size_t)k * N4H + c4, v);
}

__global__ __launch_bounds__(256)
void conv_fcw_kernel(const float* __restrict__ fcw)   // [OUT,HID] -> [HID,OUT]
{
    size_t t = (size_t)blockIdx.x * 256 + threadIdx.x;
    int k  = (int)(t / (OUT_ / 4));
    int n4 = (int)(t % (OUT_ / 4)) * 4;
    float4 v;
    v.x = fcw[(size_t)(n4 + 0) * HID_ + k];
    v.y = fcw[(size_t)(n4 + 1) * HID_ + k];
    v.z = fcw[(size_t)(n4 + 2) * HID_ + k];
    v.w = fcw[(size_t)(n4 + 3) * HID_ + k];
    split_store4(g_FThi + (size_t)k * OUT_ + n4, g_FTlo + (size_t)k * OUT_ + n4, v);
}

__global__ __launch_bounds__(256)
void conv_bias_kernel(const float* __restrict__ bi, const float* __restrict__ bf,
                      const float* __restrict__ bo, const float* __restrict__ bc)
{
    int n = blockIdx.x * 256 + threadIdx.x;
    int g = n >> 10, j = n & 1023;
    const float* b = (g == 0) ? bi : (g == 1) ? bf : (g == 2) ? bo : bc;
    g_bias[n] = b[j];
}

// ---------------------------------------------------------------------------
// Split-bf16 GEMM, BM=128 x BN=256, warp tile 64x64.
// B is [K][ldb]; the 256-col tile gathers 4 segments of 64 cols at
// colbase(seg) = nbase + seg*segstride.
//   MODE 0 (gates): nbase = bx*64, segstride = 1024 -> strips [i|f|o|c] of
//                   64 hidden units. Fused LSTM epilogue via smem staging.
//   MODE 1 (fc):    nbase = bx*256, segstride = 64 -> plain bias+store.
// ---------------------------------------------------------------------------
template<int MODE>
__global__ __launch_bounds__(NTH, 1)
void split_gemm_kernel(const __nv_bfloat16* __restrict__ Ah, const __nv_bfloat16* __restrict__ Al,
                       int lda,
                       const __nv_bfloat16* __restrict__ Bh, const __nv_bfloat16* __restrict__ Bl,
                       int ldb, int K,
                       const float* __restrict__ bias,
                       const float* __restrict__ c_t,
                       float* __restrict__ o0,       // MODE0: h_new  MODE1: out
                       float* __restrict__ o1,       // MODE0: c_new
                       __nv_bfloat16* __restrict__ Hhi, __nv_bfloat16* __restrict__ Hlo)
{
    extern __shared__ __nv_bfloat16 sm[];
    __nv_bfloat16* sAh = sm + H_AH;
    __nv_bfloat16* sAl = sm + H_AL;
    __nv_bfloat16* sBh = sm + H_BH;
    __nv_bfloat16* sBl = sm + H_BL;

    const int tid  = threadIdx.x;
    const int warp = tid >> 5, lane = tid & 31;
    const int m0   = blockIdx.y * BM;
    const int nbase  = (MODE == 0) ? blockIdx.x * 64 : blockIdx.x * BN;
    const int segstr = (MODE == 0) ? 1024 : 64;
    const int wm = (warp >> 2) * 64;
    const int wn = (warp & 3) * 64;

    float acc[4][8][4];
    #pragma unroll
    for (int mi = 0; mi < 4; mi++)
        #pragma unroll
        for (int ni = 0; ni < 8; ni++)
            #pragma unroll
            for (int q = 0; q < 4; q++) acc[mi][ni][q] = 0.0f;

    auto load_stage = [&](int s, int k0) {
        // A: 128 rows x 4 chunks of 16B (hi + lo)
        #pragma unroll
        for (int i = 0; i < 2; i++) {
            int id = i * NTH + tid;
            int row = id >> 2, c = id & 3;
            size_t go = (size_t)(m0 + row) * lda + k0 + c * 8;
            int so = s * BM * ASTR + row * ASTR + c * 8;
            cp16(sAh + so, Ah + go);
            cp16(sAl + so, Al + go);
        }
        // B: 32 rows x 4 segs x 8 chunks of 16B (hi + lo)
        #pragma unroll
        for (int i = 0; i < 4; i++) {
            int id = i * NTH + tid;
            int row = id >> 5, ch = id & 31;
            int seg = ch >> 3, c8 = ch & 7;
            size_t go = (size_t)(k0 + row) * ldb + nbase + seg * segstr + c8 * 8;
            int so = s * BK * BSTR + row * BSTR + seg * 64 + c8 * 8;
            cp16(sBh + so, Bh + go);
            cp16(sBl + so, Bl + go);
        }
    };

    load_stage(0, 0);
    cp_commit();

    const int KT = K / BK;
    const int arow = lane & 15;
    const int asub = (lane >> 4) * 8;
    const int brow = (lane & 7) + ((lane >> 3) & 1) * 8;
    const int bsub = (lane >> 4) * 8;

    for (int kt = 0; kt < KT; kt++) {
        int s = kt & 1;
        cp_wait0();
        __syncthreads();
        if (kt + 1 < KT) { load_stage(s ^ 1, (kt + 1) * BK); cp_commit(); }

        const __nv_bfloat16* pAh = sAh + s * BM * ASTR;
        const __nv_bfloat16* pAl = sAl + s * BM * ASTR;
        const __nv_bfloat16* pBh = sBh + s * BK * BSTR;
        const __nv_bfloat16* pBl = sBl + s * BK * BSTR;

        #pragma unroll
        for (int ks = 0; ks < 2; ks++) {
            uint32_t aHi[4][4], aLo[4][4], bF[8][2];
            const int ak = ks * 16 + asub;
            #pragma unroll
            for (int mi = 0; mi < 4; mi++) {
                ldm_x4(aHi[mi], pAh + (wm + mi * 16 + arow) * ASTR + ak);
                ldm_x4(aLo[mi], pAl + (wm + mi * 16 + arow) * ASTR + ak);
            }
            const int bk = ks * 16 + brow;
            #pragma unroll
            for (int nb = 0; nb < 4; nb++) {
                uint32_t r[4];
                ldm_x4t(r, pBh + bk * BSTR + wn + nb * 16 + bsub);
                bF[nb * 2 + 0][0] = r[0]; bF[nb * 2 + 0][1] = r[1];
                bF[nb * 2 + 1][0] = r[2]; bF[nb * 2 + 1][1] = r[3];
            }
            #pragma unroll
            for (int mi = 0; mi < 4; mi++)
                #pragma unroll
                for (int ni = 0; ni < 8; ni++) {
                    mma_bf16(acc[mi][ni], aHi[mi], bF[ni]);
                    mma_bf16(acc[mi][ni], aLo[mi], bF[ni]);
                }
            #pragma unroll
            for (int nb = 0; nb < 4; nb++) {
                uint32_t r[4];
                ldm_x4t(r, pBl + bk * BSTR + wn + nb * 16 + bsub);
                bF[nb * 2 + 0][0] = r[0]; bF[nb * 2 + 0][1] = r[1];
                bF[nb * 2 + 1][0] = r[2]; bF[nb * 2 + 1][1] = r[3];
            }
            #pragma unroll
            for (int mi = 0; mi < 4; mi++)
                #pragma unroll
                for (int ni = 0; ni < 8; ni++)
                    mma_bf16(acc[mi][ni], aHi[mi], bF[ni]);
        }
    }

    const int grow = lane >> 2;
    const int gcol = (lane & 3) * 2;

    if (MODE == 1) {
        // plain epilogue: +bias, store fp32
        #pragma unroll
        for (int mi = 0; mi < 4; mi++) {
            #pragma unroll
            for (int ni = 0; ni < 8; ni++) {
                int ct = wn + ni * 8 + gcol;
                int n  = nbase + ct;              // segstr=64: contiguous 256 cols
                float b0 = bias[n], b1 = bias[n + 1];
                int r0 = m0 + wm + mi * 16 + grow;
                float2 v0 = {acc[mi][ni][0] + b0, acc[mi][ni][1] + b1};
                float2 v1 = {acc[mi][ni][2] + b0, acc[mi][ni][3] + b1};
                *(float2*)&o0[(size_t)r0 * OUT_ + n] = v0;
                *(float2*)&o0[(size_t)(r0 + 8) * OUT_ + n] = v1;
            }
        }
        return;
    }

    // MODE 0: fused LSTM epilogue via smem staging, 32-row chunks
    float* S = (float*)sm;
    const int u0 = nbase;       // 64 hidden units per block
    for (int r0 = 0; r0 < BM; r0 += 32) {
        __syncthreads();   // previous chunk readers done / mainloop smem free
        #pragma unroll
        for (int mi = 0; mi < 4; mi++) {
            int rl = wm + mi * 16;
            if (rl >= r0 && rl < r0 + 32) {
                #pragma unroll
                for (int ni = 0; ni < 8; ni++) {
                    int ct  = wn + ni * 8 + gcol;
                    int seg = ct >> 6, cin = ct & 63;
                    float2 bv = *(const float2*)&g_bias[seg * 1024 + u0 + cin];
                    int rr = rl - r0 + grow;
                    float2 v0 = {acc[mi][ni][0] + bv.x, acc[mi][ni][1] + bv.y};
                    float2 v1 = {acc[mi][ni][2] + bv.x, acc[mi][ni][3] + bv.y};
                    *(float2*)&S[rr * ESTR + ct] = v0;
                    *(float2*)&S[(rr + 8) * ESTR + ct] = v1;
                }
            }
        }
        __syncthreads();
        // 256 threads process 32 rows x 64 units (8 units each)
        {
            int row = tid >> 3;
            int uo  = (tid & 7) * 8;
            int m = m0 + r0 + row;
            const float* si = S + row * ESTR;
            float4 ca = *(const float4*)&c_t[(size_t)m * HID_ + u0 + uo];
            float4 cb = *(const float4*)&c_t[(size_t)m * HID_ + u0 + uo + 4];
            float ct8[8] = {ca.x, ca.y, ca.z, ca.w, cb.x, cb.y, cb.z, cb.w};
            float hn[8], cn[8];
            #pragma unroll
            for (int j = 0; j < 8; j++) {
                float gi = sigf(si[uo + j]);
                float gf = sigf(si[64 + uo + j]);
                float go = sigf(si[128 + uo + j]);
                float gc = tanhf(si[192 + uo + j]);
                cn[j] = gf * ct8[j] + gi * gc;
                hn[j] = go * tanhf(cn[j]);
            }
            size_t off = (size_t)m * HID_ + u0 + uo;
            *(float4*)&o1[off]     = make_float4(cn[0], cn[1], cn[2], cn[3]);
            *(float4*)&o1[off + 4] = make_float4(cn[4], cn[5], cn[6], cn[7]);
            *(float4*)&o0[off]     = make_float4(hn[0], hn[1], hn[2], hn[3]);
            *(float4*)&o0[off + 4] = make_float4(hn[4], hn[5], hn[6], hn[7]);
            union { __nv_bfloat16 b[8]; uint4 u4; } H, L;
            #pragma unroll
            for (int j = 0; j < 8; j++) {
                H.b[j] = __float2bfloat16(hn[j]);
                L.b[j] = __float2bfloat16(hn[j] - __bfloat162float(H.b[j]));
            }
            *(uint4*)&Hhi[off] = H.u4;
            *(uint4*)&Hlo[off] = L.u4;
        }
    }
}

// ---------------------------------------------------------------------------
// Launch
// ---------------------------------------------------------------------------
extern "C" void kernel_launch(void* const* d_in, const int* in_sizes, int n_in,
                              void* d_out, int out_size)
{
    const float* x   = (const float*)d_in[0];
    const float* h   = (const float*)d_in[1];
    const float* c   = (const float*)d_in[2];
    const float* Wi  = (const float*)d_in[3];
    const float* Ui  = (const float*)d_in[4];
    const float* bi  = (const float*)d_in[5];
    const float* Wf  = (const float*)d_in[6];
    const float* Uf  = (const float*)d_in[7];
    const float* bf  = (const float*)d_in[8];
    const float* Wo  = (const float*)d_in[9];
    const float* Uo  = (const float*)d_in[10];
    const float* bo  = (const float*)d_in[11];
    const float* Wc  = (const float*)d_in[12];
    const float* Uc  = (const float*)d_in[13];
    const float* bc  = (const float*)d_in[14];
    const float* fcw = (const float*)d_in[15];
    const float* fcb = (const float*)d_in[16];

    float* out   = (float*)d_out;
    float* h_new = out + (size_t)B_ * OUT_;
    float* c_new = h_new + (size_t)B_ * HID_;

    cudaFuncSetAttribute(split_gemm_kernel<0>, cudaFuncAttributeMaxDynamicSharedMemorySize, SMEM_BYTES);
    cudaFuncSetAttribute(split_gemm_kernel<1>, cudaFuncAttributeMaxDynamicSharedMemorySize, SMEM_BYTES);

    void *pXh, *pXl, *pWh, *pWl, *pFh, *pFl, *pHh, *pHl, *pBias;
    cudaGetSymbolAddress(&pXh, g_Xhi);  cudaGetSymbolAddress(&pXl, g_Xlo);
    cudaGetSymbolAddress(&pWh, g_Whi);  cudaGetSymbolAddress(&pWl, g_Wlo);
    cudaGetSymbolAddress(&pFh, g_FThi); cudaGetSymbolAddress(&pFl, g_FTlo);
    cudaGetSymbolAddress(&pHh, g_Hhi);  cudaGetSymbolAddress(&pHl, g_Hlo);
    cudaGetSymbolAddress(&pBias, g_bias);

    conv_x_kernel<<<(B_ * (KC_ / 4)) / 256, 256>>>(x, h);
    conv_w_kernel<<<(KC_ * (N4H / 4)) / 256, 256>>>(Wi, Wf, Wo, Wc, Ui, Uf, Uo, Uc);
    conv_fcw_kernel<<<(HID_ * OUT_ / 4) / 256, 256>>>(fcw);
    conv_bias_kernel<<<N4H / 256, 256>>>(bi, bf, bo, bc);

    // Gates GEMM + fused LSTM cell epilogue. grid (16, 128)
    dim3 g1(HID_ / 64, B_ / BM);
    split_gemm_kernel<0><<<g1, NTH, SMEM_BYTES>>>(
        (const __nv_bfloat16*)pXh, (const __nv_bfloat16*)pXl, KC_,
        (const __nv_bfloat16*)pWh, (const __nv_bfloat16*)pWl, N4H, KC_,
        (const float*)pBias, c, h_new, c_new,
        (__nv_bfloat16*)pHh, (__nv_bfloat16*)pHl);

    // FC GEMM. grid (2, 128)
    dim3 g2(OUT_ / BN, B_ / BM);
    split_gemm_kernel<1><<<g2, NTH, SMEM_BYTES>>>(
        (const __nv_bfloat16*)pHh, (const __nv_bfloat16*)pHl, HID_,
        (const __nv_bfloat16*)pFh, (const __nv_bfloat16*)pFl, OUT_, HID_,
        fcb, nullptr, out, nullptr, nullptr, nullptr);
}

// round 6
// speedup vs baseline: 1.0679x; 1.0679x over previous
#include <cuda_runtime.h>
#include <cuda_bf16.h>
#include <math.h>
#include <stdint.h>

// Problem dims (fixed)
#define B_   16384
#define IN_  512
#define HID_ 1024
#define OUT_ 512
#define KC_  1536
#define N4H  4096

// GEMM tiling (R2-proven: 2 CTAs/SM)
#define BM 128
#define BN 128
#define BK 32
#define NTH 256
#define ASTR 40     // A smem row stride (halves)
#define BSTR 136    // B smem row stride (halves)

#define SMEM_HALVES (2*BM*ASTR + 2*BM*ASTR + 2*BK*BSTR + 2*BK*BSTR)  // 37888
#define SMEM_BYTES  (SMEM_HALVES * 2)                                 // 75776

// Epilogue staging: 32 rows x 132 f32
#define SST 132

// ---------------------------------------------------------------------------
// Static device scratch
// ---------------------------------------------------------------------------
__device__ __nv_bfloat16 g_Xhi[(size_t)B_ * KC_];
__device__ __nv_bfloat16 g_Xlo[(size_t)B_ * KC_];
__device__ __nv_bfloat16 g_Whi[(size_t)KC_ * N4H];    // [K][4H] concat [i|f|o|c]
__device__ __nv_bfloat16 g_Wlo[(size_t)KC_ * N4H];
__device__ __nv_bfloat16 g_FThi[(size_t)HID_ * OUT_]; // fc_w^T [HID][OUT]
__device__ __nv_bfloat16 g_FTlo[(size_t)HID_ * OUT_];
__device__ __nv_bfloat16 g_Hhi[(size_t)B_ * HID_];
__device__ __nv_bfloat16 g_Hlo[(size_t)B_ * HID_];
__device__ float g_bias[N4H];                         // concat [bi|bf|bo|bc]

// ---------------------------------------------------------------------------
// Helpers
// ---------------------------------------------------------------------------
__device__ __forceinline__ void split_store4(__nv_bfloat16* hi, __nv_bfloat16* lo, float4 v)
{
    float f[4] = {v.x, v.y, v.z, v.w};
    union { __nv_bfloat16 b[4]; uint2 u; } H, L;
    #pragma unroll
    for (int i = 0; i < 4; i++) {
        H.b[i] = __float2bfloat16(f[i]);
        L.b[i] = __float2bfloat16(f[i] - __bfloat162float(H.b[i]));
    }
    *(uint2*)hi = H.u;
    *(uint2*)lo = L.u;
}

__device__ __forceinline__ void cp16(void* sdst, const void* gsrc)
{
    uint32_t s = (uint32_t)__cvta_generic_to_shared(sdst);
    asm volatile("cp.async.cg.shared.global [%0], [%1], 16;" :: "r"(s), "l"(gsrc));
}
__device__ __forceinline__ void cp_commit() { asm volatile("cp.async.commit_group;"); }
__device__ __forceinline__ void cp_wait0()  { asm volatile("cp.async.wait_group 0;"); }

__device__ __forceinline__ void ldm_x4(uint32_t* r, const __nv_bfloat16* p)
{
    uint32_t a = (uint32_t)__cvta_generic_to_shared(p);
    asm volatile("ldmatrix.sync.aligned.m8n8.x4.shared.b16 {%0,%1,%2,%3}, [%4];"
                 : "=r"(r[0]), "=r"(r[1]), "=r"(r[2]), "=r"(r[3]) : "r"(a));
}
__device__ __forceinline__ void ldm_x4t(uint32_t* r, const __nv_bfloat16* p)
{
    uint32_t a = (uint32_t)__cvta_generic_to_shared(p);
    asm volatile("ldmatrix.sync.aligned.m8n8.x4.trans.shared.b16 {%0,%1,%2,%3}, [%4];"
                 : "=r"(r[0]), "=r"(r[1]), "=r"(r[2]), "=r"(r[3]) : "r"(a));
}
__device__ __forceinline__ void mma_bf16(float* c, const uint32_t* a, const uint32_t* b)
{
    asm volatile(
        "mma.sync.aligned.m16n8k16.row.col.f32.bf16.bf16.f32 "
        "{%0,%1,%2,%3}, {%4,%5,%6,%7}, {%8,%9}, {%0,%1,%2,%3};"
        : "+f"(c[0]), "+f"(c[1]), "+f"(c[2]), "+f"(c[3])
        : "r"(a[0]), "r"(a[1]), "r"(a[2]), "r"(a[3]), "r"(b[0]), "r"(b[1]));
}

__device__ __forceinline__ float sigf(float v) { return 1.0f / (1.0f + __expf(-v)); }

// ---------------------------------------------------------------------------
// Conversion kernels (R2-proven)
// ---------------------------------------------------------------------------
__global__ __launch_bounds__(256)
void conv_x_kernel(const float* __restrict__ x, const float* __restrict__ h)
{
    size_t t = (size_t)blockIdx.x * 256 + threadIdx.x;
    size_t m = t / (KC_ / 4);
    int c4 = (int)(t % (KC_ / 4)) * 4;
    float4 v = (c4 < IN_) ? *(const float4*)&x[m * IN_ + c4]
                          : *(const float4*)&h[m * HID_ + (c4 - IN_)];
    split_store4(g_Xhi + m * KC_ + c4, g_Xlo + m * KC_ + c4, v);
}

__global__ __launch_bounds__(256)
void conv_w_kernel(const float* __restrict__ Wi, const float* __restrict__ Wf,
                   const float* __restrict__ Wo, const float* __restrict__ Wc,
                   const float* __restrict__ Ui, const float* __restrict__ Uf,
                   const float* __restrict__ Uo, const float* __restrict__ Uc)
{
    size_t t = (size_t)blockIdx.x * 256 + threadIdx.x;
    int k  = (int)(t / (N4H / 4));
    int c4 = (int)(t % (N4H / 4)) * 4;
    int g  = c4 >> 10;
    int j  = c4 & 1023;
    const float* W = (g == 0) ? Wi : (g == 1) ? Wf : (g == 2) ? Wo : Wc;
    const float* U = (g == 0) ? Ui : (g == 1) ? Uf : (g == 2) ? Uo : Uc;
    float4 v = (k < IN_) ? *(const float4*)&W[(size_t)k * HID_ + j]
                         : *(const float4*)&U[(size_t)(k - IN_) * HID_ + j];
    split_store4(g_Whi + (size_t)k * N4H + c4, g_Wlo + (size_t)k * N4H + c4, v);
}

__global__ __launch_bounds__(256)
void conv_fcw_kernel(const float* __restrict__ fcw)   // [OUT,HID] -> [HID,OUT]
{
    size_t t = (size_t)blockIdx.x * 256 + threadIdx.x;
    int k  = (int)(t / (OUT_ / 4));
    int n4 = (int)(t % (OUT_ / 4)) * 4;
    float4 v;
    v.x = fcw[(size_t)(n4 + 0) * HID_ + k];
    v.y = fcw[(size_t)(n4 + 1) * HID_ + k];
    v.z = fcw[(size_t)(n4 + 2) * HID_ + k];
    v.w = fcw[(size_t)(n4 + 3) * HID_ + k];
    split_store4(g_FThi + (size_t)k * OUT_ + n4, g_FTlo + (size_t)k * OUT_ + n4, v);
}

__global__ __launch_bounds__(256)
void conv_bias_kernel(const float* __restrict__ bi, const float* __restrict__ bf,
                      const float* __restrict__ bo, const float* __restrict__ bc)
{
    int n = blockIdx.x * 256 + threadIdx.x;
    int g = n >> 10, j = n & 1023;
    const float* b = (g == 0) ? bi : (g == 1) ? bf : (g == 2) ? bo : bc;
    g_bias[n] = b[j];
}

// ---------------------------------------------------------------------------
// Split-bf16 GEMM (R2 geometry): BM=128 x BN=128, warp tile 64x32, 8 warps.
// B cols gathered as 4 segments of 32 at colbase(seg) = nbase + seg*segstr.
//   MODE 0 (gates): nbase = bx*32, segstr = 1024 -> [i|f|o|c] strips of 32
//                   hidden units; fused LSTM epilogue via smem staging.
//   MODE 1 (fc):    nbase = bx*128, segstr = 32 -> contiguous; bias+store.
// ---------------------------------------------------------------------------
template<int MODE>
__global__ __launch_bounds__(NTH, 2)
void split_gemm_kernel(const __nv_bfloat16* __restrict__ Ah, const __nv_bfloat16* __restrict__ Al,
                       int lda,
                       const __nv_bfloat16* __restrict__ Bh, const __nv_bfloat16* __restrict__ Bl,
                       int ldb, int K,
                       const float* __restrict__ bias,
                       const float* __restrict__ c_t,
                       float* __restrict__ o0,       // MODE0: h_new  MODE1: out
                       float* __restrict__ o1,       // MODE0: c_new
                       __nv_bfloat16* __restrict__ Hhi, __nv_bfloat16* __restrict__ Hlo)
{
    extern __shared__ __nv_bfloat16 sm[];
    __nv_bfloat16* sAh = sm;
    __nv_bfloat16* sAl = sAh + 2 * BM * ASTR;
    __nv_bfloat16* sBh = sAl + 2 * BM * ASTR;
    __nv_bfloat16* sBl = sBh + 2 * BK * BSTR;

    const int tid  = threadIdx.x;
    const int warp = tid >> 5, lane = tid & 31;
    const int m0   = blockIdx.y * BM;
    const int nbase  = (MODE == 0) ? blockIdx.x * 32 : blockIdx.x * BN;
    const int segstr = (MODE == 0) ? 1024 : 32;
    const int wm = (warp >> 2) * 64;
    const int wn = (warp & 3) * 32;

    float acc[4][4][4];
    #pragma unroll
    for (int mi = 0; mi < 4; mi++)
        #pragma unroll
        for (int ni = 0; ni < 4; ni++)
            #pragma unroll
            for (int q = 0; q < 4; q++) acc[mi][ni][q] = 0.0f;

    auto load_stage = [&](int s, int k0) {
        #pragma unroll
        for (int i = 0; i < 2; i++) {              // A: 128 rows x 4 chunks 16B
            int c = tid + i * 256;
            int row = c >> 2, q = (c & 3) * 8;
            size_t go = (size_t)(m0 + row) * lda + k0 + q;
            int so = s * BM * ASTR + row * ASTR + q;
            cp16(sAh + so, Ah + go);
            cp16(sAl + so, Al + go);
        }
        #pragma unroll
        for (int i = 0; i < 2; i++) {              // B: 32 rows x 16 chunks 16B
            int c = tid + i * 256;
            int row = c >> 4, ch = c & 15;
            int seg = ch >> 2, c8 = (ch & 3) * 8;  // 4 chunks of 8 halves per seg
            size_t go = (size_t)(k0 + row) * ldb + nbase + seg * segstr + c8;
            int so = s * BK * BSTR + row * BSTR + seg * 32 + c8;
            cp16(sBh + so, Bh + go);
            cp16(sBl + so, Bl + go);
        }
    };

    load_stage(0, 0);
    cp_commit();

    const int KT = K / BK;
    const int arow = lane & 15;
    const int asub = (lane >> 4) * 8;
    const int brow = (lane & 7) + ((lane >> 3) & 1) * 8;
    const int bsub = (lane >> 4) * 8;

    for (int kt = 0; kt < KT; kt++) {
        int s = kt & 1;
        cp_wait0();
        __syncthreads();
        if (kt + 1 < KT) { load_stage(s ^ 1, (kt + 1) * BK); cp_commit(); }

        const __nv_bfloat16* pAh = sAh + s * BM * ASTR;
        const __nv_bfloat16* pAl = sAl + s * BM * ASTR;
        const __nv_bfloat16* pBh = sBh + s * BK * BSTR;
        const __nv_bfloat16* pBl = sBl + s * BK * BSTR;

        #pragma unroll
        for (int ks = 0; ks < 2; ks++) {
            uint32_t aHi[4][4], aLo[4][4], bF[4][2];
            const int ak = ks * 16 + asub;
            #pragma unroll
            for (int mi = 0; mi < 4; mi++) {
                ldm_x4(aHi[mi], pAh + (wm + mi * 16 + arow) * ASTR + ak);
                ldm_x4(aLo[mi], pAl + (wm + mi * 16 + arow) * ASTR + ak);
            }
            const int bk = ks * 16 + brow;
            #pragma unroll
            for (int nb = 0; nb < 2; nb++) {
                uint32_t r[4];
                ldm_x4t(r, pBh + bk * BSTR + wn + nb * 16 + bsub);
                bF[nb * 2 + 0][0] = r[0]; bF[nb * 2 + 0][1] = r[1];
                bF[nb * 2 + 1][0] = r[2]; bF[nb * 2 + 1][1] = r[3];
            }
            #pragma unroll
            for (int mi = 0; mi < 4; mi++)
                #pragma unroll
                for (int ni = 0; ni < 4; ni++) {
                    mma_bf16(acc[mi][ni], aHi[mi], bF[ni]);
                    mma_bf16(acc[mi][ni], aLo[mi], bF[ni]);
                }
            #pragma unroll
            for (int nb = 0; nb < 2; nb++) {
                uint32_t r[4];
                ldm_x4t(r, pBl + bk * BSTR + wn + nb * 16 + bsub);
                bF[nb * 2 + 0][0] = r[0]; bF[nb * 2 + 0][1] = r[1];
                bF[nb * 2 + 1][0] = r[2]; bF[nb * 2 + 1][1] = r[3];
            }
            #pragma unroll
            for (int mi = 0; mi < 4; mi++)
                #pragma unroll
                for (int ni = 0; ni < 4; ni++)
                    mma_bf16(acc[mi][ni], aHi[mi], bF[ni]);
        }
    }

    const int grow = lane >> 2;
    const int gcol = (lane & 3) * 2;

    if (MODE == 1) {
        #pragma unroll
        for (int mi = 0; mi < 4; mi++) {
            #pragma unroll
            for (int ni = 0; ni < 4; ni++) {
                int n = nbase + wn + ni * 8 + gcol;
                float b0 = bias[n], b1 = bias[n + 1];
                int r0 = m0 + wm + mi * 16 + grow;
                float2 v0 = {acc[mi][ni][0] + b0, acc[mi][ni][1] + b1};
                float2 v1 = {acc[mi][ni][2] + b0, acc[mi][ni][3] + b1};
                *(float2*)&o0[(size_t)r0 * OUT_ + n] = v0;
                *(float2*)&o0[(size_t)(r0 + 8) * OUT_ + n] = v1;
            }
        }
        return;
    }

    // MODE 0: fused LSTM epilogue via smem staging, 32-row chunks.
    // Tile cols: ct = seg*32 + cin; seg = gate, unit = u0 + cin.
    float* S = (float*)sm;
    const int u0 = nbase;
    for (int r0 = 0; r0 < BM; r0 += 32) {
        __syncthreads();   // mainloop smem free / previous chunk readers done
        #pragma unroll
        for (int mi = 0; mi < 4; mi++) {
            int rl = wm + mi * 16;
            if (rl >= r0 && rl < r0 + 32) {
                #pragma unroll
                for (int ni = 0; ni < 4; ni++) {
                    int ct  = wn + ni * 8 + gcol;
                    int seg = ct >> 5, cin = ct & 31;
                    float2 bv = *(const float2*)&g_bias[seg * 1024 + u0 + cin];
                    int rr = rl - r0 + grow;
                    float2 v0 = {acc[mi][ni][0] + bv.x, acc[mi][ni][1] + bv.y};
                    float2 v1 = {acc[mi][ni][2] + bv.x, acc[mi][ni][3] + bv.y};
                    *(float2*)&S[rr * SST + ct] = v0;
                    *(float2*)&S[(rr + 8) * SST + ct] = v1;
                }
            }
        }
        __syncthreads();
        // 256 threads: 32 rows x 32 units, 4 units per thread
        {
            int row = tid >> 3;
            int uo  = (tid & 7) * 4;
            int m = m0 + r0 + row;
            const float* si = S + row * SST;
            float4 ca = *(const float4*)&c_t[(size_t)m * HID_ + u0 + uo];
            float ct4[4] = {ca.x, ca.y, ca.z, ca.w};
            float hn[4], cn[4];
            #pragma unroll
            for (int j = 0; j < 4; j++) {
                float gi = sigf(si[uo + j]);
                float gf = sigf(si[32 + uo + j]);
                float go = sigf(si[64 + uo + j]);
                float gc = tanhf(si[96 + uo + j]);
                cn[j] = gf * ct4[j] + gi * gc;
                hn[j] = go * tanhf(cn[j]);
            }
            size_t off = (size_t)m * HID_ + u0 + uo;
            *(float4*)&o1[off] = make_float4(cn[0], cn[1], cn[2], cn[3]);
            *(float4*)&o0[off] = make_float4(hn[0], hn[1], hn[2], hn[3]);
            union { __nv_bfloat16 b[4]; uint2 u; } H, L;
            #pragma unroll
            for (int j = 0; j < 4; j++) {
                H.b[j] = __float2bfloat16(hn[j]);
                L.b[j] = __float2bfloat16(hn[j] - __bfloat162float(H.b[j]));
            }
            *(uint2*)&Hhi[off] = H.u;
            *(uint2*)&Hlo[off] = L.u;
        }
    }
}

// ---------------------------------------------------------------------------
// Launch
// ---------------------------------------------------------------------------
extern "C" void kernel_launch(void* const* d_in, const int* in_sizes, int n_in,
                              void* d_out, int out_size)
{
    const float* x   = (const float*)d_in[0];
    const float* h   = (const float*)d_in[1];
    const float* c   = (const float*)d_in[2];
    const float* Wi  = (const float*)d_in[3];
    const float* Ui  = (const float*)d_in[4];
    const float* bi  = (const float*)d_in[5];
    const float* Wf  = (const float*)d_in[6];
    const float* Uf  = (const float*)d_in[7];
    const float* bf  = (const float*)d_in[8];
    const float* Wo  = (const float*)d_in[9];
    const float* Uo  = (const float*)d_in[10];
    const float* bo  = (const float*)d_in[11];
    const float* Wc  = (const float*)d_in[12];
    const float* Uc  = (const float*)d_in[13];
    const float* bc  = (const float*)d_in[14];
    const float* fcw = (const float*)d_in[15];
    const float* fcb = (const float*)d_in[16];

    float* out   = (float*)d_out;
    float* h_new = out + (size_t)B_ * OUT_;
    float* c_new = h_new + (size_t)B_ * HID_;

    cudaFuncSetAttribute(split_gemm_kernel<0>, cudaFuncAttributeMaxDynamicSharedMemorySize, SMEM_BYTES);
    cudaFuncSetAttribute(split_gemm_kernel<1>, cudaFuncAttributeMaxDynamicSharedMemorySize, SMEM_BYTES);

    void *pXh, *pXl, *pWh, *pWl, *pFh, *pFl, *pHh, *pHl, *pBias;
    cudaGetSymbolAddress(&pXh, g_Xhi);  cudaGetSymbolAddress(&pXl, g_Xlo);
    cudaGetSymbolAddress(&pWh, g_Whi);  cudaGetSymbolAddress(&pWl, g_Wlo);
    cudaGetSymbolAddress(&pFh, g_FThi); cudaGetSymbolAddress(&pFl, g_FTlo);
    cudaGetSymbolAddress(&pHh, g_Hhi);  cudaGetSymbolAddress(&pHl, g_Hlo);
    cudaGetSymbolAddress(&pBias, g_bias);

    conv_x_kernel<<<(B_ * (KC_ / 4)) / 256, 256>>>(x, h);
    conv_w_kernel<<<(KC_ * (N4H / 4)) / 256, 256>>>(Wi, Wf, Wo, Wc, Ui, Uf, Uo, Uc);
    conv_fcw_kernel<<<(HID_ * OUT_ / 4) / 256, 256>>>(fcw);
    conv_bias_kernel<<<N4H / 256, 256>>>(bi, bf, bo, bc);

    // Gates GEMM + fused LSTM cell epilogue. grid (32, 128)
    dim3 g1(HID_ / 32, B_ / BM);
    split_gemm_kernel<0><<<g1, NTH, SMEM_BYTES>>>(
        (const __nv_bfloat16*)pXh, (const __nv_bfloat16*)pXl, KC_,
        (const __nv_bfloat16*)pWh, (const __nv_bfloat16*)pWl, N4H, KC_,
        (const float*)pBias, c, h_new, c_new,
        (__nv_bfloat16*)pHh, (__nv_bfloat16*)pHl);

    // FC GEMM. grid (4, 128)
    dim3 g2(OUT_ / BN, B_ / BM);
    split_gemm_kernel<1><<<g2, NTH, SMEM_BYTES>>>(
        (const __nv_bfloat16*)pHh, (const __nv_bfloat16*)pHl, HID_,
        (const __nv_bfloat16*)pFh, (const __nv_bfloat16*)pFl, OUT_, HID_,
        fcb, nullptr, out, nullptr, nullptr, nullptr);
}